// round 2
// baseline (speedup 1.0000x reference)
#include <cuda_runtime.h>
#include <cstdint>
#include <cstddef>

#define LL 32
#define HH 128
#define KD 130
#define SPB 4
#define NBLK 128
#define NTHR 128
#define NCELL 1024
#define EPSF 1e-8f
#define W_BYTES 66560u
#define SM_BYTES 512u
#define TX_BYTES (W_BYTES + 2u * SM_BYTES)

struct __align__(16) Smem {
    float W[2][HH * KD];
    float bvec[2][HH];
    float wfvec[2][HH];
    float smp[SPB][NCELL];
    float hv[SPB][LL][HH];
    float inp[2][KD][SPB];
    float red[2][4][SPB];
    unsigned long long mbar[2];
};

__device__ __forceinline__ uint32_t s2u(const void* p) {
    return (uint32_t)__cvta_generic_to_shared(p);
}
__device__ __forceinline__ void mbar_init(uint32_t a, uint32_t cnt) {
    asm volatile("mbarrier.init.shared::cta.b64 [%0], %1;" :: "r"(a), "r"(cnt) : "memory");
}
__device__ __forceinline__ void mbar_expect(uint32_t a, uint32_t tx) {
    asm volatile("mbarrier.arrive.expect_tx.shared::cta.b64 _, [%0], %1;" :: "r"(a), "r"(tx) : "memory");
}
__device__ __forceinline__ void tma1d(uint32_t dst, const void* src, uint32_t bytes, uint32_t mbar) {
    asm volatile("cp.async.bulk.shared::cluster.global.mbarrier::complete_tx::bytes [%0], [%1], %2, [%3];"
                 :: "r"(dst), "l"(src), "r"(bytes), "r"(mbar) : "memory");
}
__device__ __forceinline__ void mbar_wait(uint32_t a, uint32_t phase) {
    uint32_t done = 0;
    while (!done) {
        asm volatile("{\n\t.reg .pred p;\n\t"
                     "mbarrier.try_wait.parity.acquire.cta.shared::cta.b64 p, [%1], %2;\n\t"
                     "selp.b32 %0, 1, 0, p;\n\t}"
                     : "=r"(done) : "r"(a), "r"(phase) : "memory");
    }
}
__device__ __forceinline__ float tanh_fast(float x) {
    float y; asm("tanh.approx.f32 %0, %1;" : "=f"(y) : "f"(x)); return y;
}

__global__ void __launch_bounds__(NTHR, 1)
rnn2d_kernel(const float* __restrict__ gS, const float* __restrict__ gW,
             const float* __restrict__ gB, const float* __restrict__ gWf,
             const float* __restrict__ gBf, float* __restrict__ out)
{
    extern __shared__ unsigned char smem_raw[];
    Smem& s = *reinterpret_cast<Smem*>(smem_raw);
    const int tid = threadIdx.x;
    const int blk = blockIdx.x;

    const float* gs = gS + (size_t)blk * SPB * NCELL;
    for (int t = tid; t < SPB * NCELL; t += NTHR) ((float*)s.smp)[t] = gs[t];
    for (int t = tid; t < SPB * LL * HH; t += NTHR) ((float*)s.hv)[t] = 0.f;
    {
        float4 z = make_float4(0.f, 0.f, 0.f, 0.f);
        *(float4*)&s.inp[0][2 + tid][0] = z;
        if (tid == 0) {
            *(float4*)&s.inp[0][0][0] = z;
            *(float4*)&s.inp[0][1][0] = make_float4(2.f, 2.f, 2.f, 2.f);
        }
    }
    const uint32_t mb0 = s2u(&s.mbar[0]);
    const uint32_t mb1 = s2u(&s.mbar[1]);
    if (tid == 0) {
        mbar_init(mb0, 1);
        mbar_init(mb1, 1);
        asm volatile("fence.mbarrier_init.release.cluster;" ::: "memory");
    }
    __syncthreads();

    if (tid == 0) {
        mbar_expect(mb0, TX_BYTES);
        tma1d(s2u(&s.W[0][0]),     gW,  W_BYTES,  mb0);
        tma1d(s2u(&s.bvec[0][0]),  gB,  SM_BYTES, mb0);
        tma1d(s2u(&s.wfvec[0][0]), gWf, SM_BYTES, mb0);
    }

    float lp = 0.f;

    for (int c = 0; c < NCELL; ++c) {
        const int buf = c & 1;
        const int r = c >> 5, j = c & 31;
        const int col = (r & 1) ? (LL - 1 - j) : j;
        const int cell = (r << 5) + col;

        if (tid == 0 && c + 1 < NCELL) {
            const int cn = c + 1, rn = cn >> 5, jn = cn & 31;
            const int coln = (rn & 1) ? (LL - 1 - jn) : jn;
            const int celln = (rn << 5) + coln;
            const uint32_t mb = buf ? mb0 : mb1;
            mbar_expect(mb, TX_BYTES);
            tma1d(s2u(&s.W[buf ^ 1][0]),     gW  + (size_t)celln * HH * KD, W_BYTES,  mb);
            tma1d(s2u(&s.bvec[buf ^ 1][0]),  gB  + celln * HH,              SM_BYTES, mb);
            tma1d(s2u(&s.wfvec[buf ^ 1][0]), gWf + celln * HH,              SM_BYTES, mb);
        }
        mbar_wait(buf ? mb1 : mb0, (c >> 1) & 1);

        const float* Wr = &s.W[buf][tid * KD];
        const float bi2 = 2.f * s.bvec[buf][tid];
        float a0 = bi2, a1 = bi2, a2 = bi2, a3 = bi2;
        const float (*ip)[SPB] = s.inp[buf];
        #pragma unroll
        for (int k = 0; k < KD; k += 2) {
            const float2 w = *(const float2*)(Wr + k);
            const float4 i0 = *(const float4*)&ip[k][0];
            const float4 i1 = *(const float4*)&ip[k + 1][0];
            a0 += w.x * i0.x; a1 += w.x * i0.y; a2 += w.x * i0.z; a3 += w.x * i0.w;
            a0 += w.y * i1.x; a1 += w.y * i1.y; a2 += w.y * i1.z; a3 += w.y * i1.w;
        }
        const float wfi = s.wfvec[buf][tid];
        const float h0 = tanh_fast(a0), h1 = tanh_fast(a1);
        const float h2 = tanh_fast(a2), h3 = tanh_fast(a3);

        s.hv[0][col][tid] = h0; s.hv[1][col][tid] = h1;
        s.hv[2][col][tid] = h2; s.hv[3][col][tid] = h3;

        float p0 = wfi * h0, p1 = wfi * h1, p2 = wfi * h2, p3 = wfi * h3;
        #pragma unroll
        for (int o = 16; o; o >>= 1) {
            p0 += __shfl_xor_sync(0xffffffffu, p0, o);
            p1 += __shfl_xor_sync(0xffffffffu, p1, o);
            p2 += __shfl_xor_sync(0xffffffffu, p2, o);
            p3 += __shfl_xor_sync(0xffffffffu, p3, o);
        }
        if ((tid & 31) == 0) {
            const int w = tid >> 5;
            s.red[buf][w][0] = p0; s.red[buf][w][1] = p1;
            s.red[buf][w][2] = p2; s.red[buf][w][3] = p3;
        }

        if (c + 1 < NCELL) {
            const int cn = c + 1, rn = cn >> 5, jn = cn & 31;
            const int coln = (rn & 1) ? (LL - 1 - jn) : jn;
            float4 v;
            if (jn == 0) {
                v.x = s.hv[0][coln][tid]; v.y = s.hv[1][coln][tid];
                v.z = s.hv[2][coln][tid]; v.w = s.hv[3][coln][tid];
            } else {
                v.x = h0 + s.hv[0][coln][tid]; v.y = h1 + s.hv[1][coln][tid];
                v.z = h2 + s.hv[2][coln][tid]; v.w = h3 + s.hv[3][coln][tid];
            }
            *(float4*)&s.inp[buf ^ 1][2 + tid][0] = v;
            if (tid == 0) {
                float4 e0, e1;
                float* x0 = &e0.x; float* x1 = &e1.x;
                #pragma unroll
                for (int si = 0; si < SPB; ++si) {
                    const float xh = (jn == 0) ? 0.f : s.smp[si][(rn << 5) + col];
                    const float xv = (rn == 0) ? 0.f : s.smp[si][((rn - 1) << 5) + coln];
                    x0[si] = xh + xv;
                    x1[si] = 2.f - xh - xv;
                }
                *(float4*)&s.inp[buf ^ 1][0][0] = e0;
                *(float4*)&s.inp[buf ^ 1][1][0] = e1;
            }
        }
        __syncthreads();

        if (tid < SPB) {
            const float dot = s.red[buf][0][tid] + s.red[buf][1][tid]
                            + s.red[buf][2][tid] + s.red[buf][3][tid];
            const float pre = dot + __ldg(gBf + cell);
            const float xhat = 1.f / (1.f + expf(-pre));
            const float m = s.smp[tid][cell];
            lp += m * logf(xhat + EPSF) + (1.f - m) * logf(1.f - xhat + EPSF);
        }
    }

    if (tid < SPB) out[blk * SPB + tid] = lp;
}

extern "C" void kernel_launch(void* const* d_in, const int* in_sizes, int n_in,
                              void* d_out, int out_size) {
    const float* samples = (const float*)d_in[0];
    const float* W1      = (const float*)d_in[1];
    const float* b1      = (const float*)d_in[2];
    const float* Wf      = (const float*)d_in[3];
    const float* bf      = (const float*)d_in[4];
    float* out = (float*)d_out;
    const size_t smem = sizeof(Smem);
    cudaFuncSetAttribute(rnn2d_kernel, cudaFuncAttributeMaxDynamicSharedMemorySize, (int)smem);
    rnn2d_kernel<<<NBLK, NTHR, smem>>>(samples, W1, b1, Wf, bf, out);
}

// round 3
// speedup vs baseline: 1.0032x; 1.0032x over previous
#include <cuda_runtime.h>
#include <cstdint>
#include <cstddef>

#define LL 32
#define HH 128
#define KD 130
#define KP 132              // padded K (row stride), 132 % 32 == 4 -> conflict-free LDS.128
#define SPB 4
#define NBLK 128
#define NTHR 128
#define NCELL 1024
#define EPSF 1e-8f
#define W_BYTES  (HH * KP * 4u)          // 67584
#define SM_BYTES 512u
#define TX_BYTES (W_BYTES + 2u * SM_BYTES)

// padded, per-cell weight tiles: [cell][neuron][132]
__device__ float g_Wp[(size_t)NCELL * HH * KP];

struct __align__(16) Smem {
    float W[2][HH * KP];         // 135168
    float bvec[2][HH];           //   1024
    float wfvec[2][HH];          //   1024
    float hv[SPB][LL][HH];       //  65536
    float inp[2][KP][SPB];       //   4224
    float red[2][4][SPB];        //    128
    float pre[NCELL][SPB];       //  16384
    uint32_t sbits[SPB][LL];     //    512
    unsigned long long mbar[2];  //     16
};                               // total 224016 B

__device__ __forceinline__ uint32_t s2u(const void* p) {
    return (uint32_t)__cvta_generic_to_shared(p);
}
__device__ __forceinline__ void mbar_init(uint32_t a, uint32_t cnt) {
    asm volatile("mbarrier.init.shared::cta.b64 [%0], %1;" :: "r"(a), "r"(cnt) : "memory");
}
__device__ __forceinline__ void mbar_expect(uint32_t a, uint32_t tx) {
    asm volatile("mbarrier.arrive.expect_tx.shared::cta.b64 _, [%0], %1;" :: "r"(a), "r"(tx) : "memory");
}
__device__ __forceinline__ void tma1d(uint32_t dst, const void* src, uint32_t bytes, uint32_t mbar) {
    asm volatile("cp.async.bulk.shared::cluster.global.mbarrier::complete_tx::bytes [%0], [%1], %2, [%3];"
                 :: "r"(dst), "l"(src), "r"(bytes), "r"(mbar) : "memory");
}
__device__ __forceinline__ void mbar_wait(uint32_t a, uint32_t phase) {
    uint32_t done = 0;
    while (!done) {
        asm volatile("{\n\t.reg .pred p;\n\t"
                     "mbarrier.try_wait.parity.acquire.cta.shared::cta.b64 p, [%1], %2;\n\t"
                     "selp.b32 %0, 1, 0, p;\n\t}"
                     : "=r"(done) : "r"(a), "r"(phase) : "memory");
    }
}
__device__ __forceinline__ float tanh_fast(float x) {
    float y; asm("tanh.approx.f32 %0, %1;" : "=f"(y) : "f"(x)); return y;
}

// ---------------- prep: pad W rows 130 -> 132 (zeros in the tail) ----------------
__global__ void prep_kernel(const float* __restrict__ gW) {
    const int c = blockIdx.x;
    const float* src = gW + (size_t)c * (HH * KD);
    float* dst = g_Wp + (size_t)c * (HH * KP);
    for (int t = threadIdx.x; t < HH * KP; t += blockDim.x) {
        const int row = t / KP, col = t - row * KP;
        dst[t] = (col < KD) ? src[row * KD + col] : 0.f;
    }
}

// ---------------- main persistent kernel ----------------
__global__ void __launch_bounds__(NTHR, 1)
rnn2d_kernel(const float* __restrict__ gS, const float* __restrict__ gB,
             const float* __restrict__ gWf, const float* __restrict__ gBf,
             float* __restrict__ out)
{
    extern __shared__ unsigned char smem_raw[];
    Smem& s = *reinterpret_cast<Smem*>(smem_raw);
    const int tid = threadIdx.x;
    const int blk = blockIdx.x;

    // -- init: pack spins to bits, zero hv, zero inp, seed inp[0] --
    const float* gs = gS + (size_t)blk * SPB * NCELL;
    {
        const int sm = tid >> 5, row = tid & 31;   // 128 threads = 4 samples x 32 rows
        const float* rp = gs + sm * NCELL + row * LL;
        uint32_t bits = 0;
        #pragma unroll
        for (int j = 0; j < LL; ++j) bits |= (rp[j] > 0.5f ? 1u : 0u) << j;
        s.sbits[sm][row] = bits;
    }
    for (int t = tid; t < SPB * LL * HH; t += NTHR) ((float*)s.hv)[t] = 0.f;
    for (int t = tid; t < 2 * KP * SPB; t += NTHR) ((float*)s.inp)[t] = 0.f;
    __syncthreads();
    if (tid == 0)
        *(float4*)&s.inp[0][1][0] = make_float4(2.f, 2.f, 2.f, 2.f);  // (1-xh)+(1-xv) at cell 0

    const uint32_t mb0 = s2u(&s.mbar[0]);
    const uint32_t mb1 = s2u(&s.mbar[1]);
    if (tid == 0) {
        mbar_init(mb0, 1);
        mbar_init(mb1, 1);
        asm volatile("fence.mbarrier_init.release.cluster;" ::: "memory");
    }
    __syncthreads();

    if (tid == 0) {
        mbar_expect(mb0, TX_BYTES);
        tma1d(s2u(&s.W[0][0]),     g_Wp, W_BYTES,  mb0);
        tma1d(s2u(&s.bvec[0][0]),  gB,   SM_BYTES, mb0);
        tma1d(s2u(&s.wfvec[0][0]), gWf,  SM_BYTES, mb0);
    }

    for (int c = 0; c < NCELL; ++c) {
        const int buf = c & 1;
        const int r = c >> 5, j = c & 31;
        const int col = (r & 1) ? (LL - 1 - j) : j;
        const int cell = (r << 5) + col;

        // prefetch next cell's parameters
        if (tid == 0 && c + 1 < NCELL) {
            const int cn = c + 1, rn = cn >> 5, jn = cn & 31;
            const int coln = (rn & 1) ? (LL - 1 - jn) : jn;
            const int celln = (rn << 5) + coln;
            const uint32_t mb = buf ? mb0 : mb1;
            mbar_expect(mb, TX_BYTES);
            tma1d(s2u(&s.W[buf ^ 1][0]),     g_Wp + (size_t)celln * HH * KP, W_BYTES,  mb);
            tma1d(s2u(&s.bvec[buf ^ 1][0]),  gB  + celln * HH,               SM_BYTES, mb);
            tma1d(s2u(&s.wfvec[buf ^ 1][0]), gWf + celln * HH,               SM_BYTES, mb);
        }
        mbar_wait(buf ? mb1 : mb0, (c >> 1) & 1);

        // -- matvec: thread = neuron, 4 sample accumulators, conflict-free LDS.128 --
        const float* Wr = &s.W[buf][tid * KP];
        const float bi2 = 2.f * s.bvec[buf][tid];
        float a0 = bi2, a1 = bi2, a2 = bi2, a3 = bi2;
        const float (*ip)[SPB] = s.inp[buf];
        #pragma unroll
        for (int k = 0; k < KP; k += 4) {
            const float4 w  = *(const float4*)(Wr + k);
            const float4 i0 = *(const float4*)&ip[k + 0][0];
            const float4 i1 = *(const float4*)&ip[k + 1][0];
            const float4 i2 = *(const float4*)&ip[k + 2][0];
            const float4 i3 = *(const float4*)&ip[k + 3][0];
            a0 += w.x * i0.x; a1 += w.x * i0.y; a2 += w.x * i0.z; a3 += w.x * i0.w;
            a0 += w.y * i1.x; a1 += w.y * i1.y; a2 += w.y * i1.z; a3 += w.y * i1.w;
            a0 += w.z * i2.x; a1 += w.z * i2.y; a2 += w.z * i2.z; a3 += w.z * i2.w;
            a0 += w.w * i3.x; a1 += w.w * i3.y; a2 += w.w * i3.z; a3 += w.w * i3.w;
        }
        const float wfi = s.wfvec[buf][tid];
        const float h0 = tanh_fast(a0), h1 = tanh_fast(a1);
        const float h2 = tanh_fast(a2), h3 = tanh_fast(a3);

        s.hv[0][col][tid] = h0; s.hv[1][col][tid] = h1;
        s.hv[2][col][tid] = h2; s.hv[3][col][tid] = h3;

        // fc-head partials: butterfly reduce within warp, per-warp to smem
        float p0 = wfi * h0, p1 = wfi * h1, p2 = wfi * h2, p3 = wfi * h3;
        #pragma unroll
        for (int o = 16; o; o >>= 1) {
            p0 += __shfl_xor_sync(0xffffffffu, p0, o);
            p1 += __shfl_xor_sync(0xffffffffu, p1, o);
            p2 += __shfl_xor_sync(0xffffffffu, p2, o);
            p3 += __shfl_xor_sync(0xffffffffu, p3, o);
        }
        if ((tid & 31) == 0) {
            const int w = tid >> 5;
            s.red[buf][w][0] = p0; s.red[buf][w][1] = p1;
            s.red[buf][w][2] = p2; s.red[buf][w][3] = p3;
        }

        // build next cell's input into the other inp buffer
        if (c + 1 < NCELL) {
            const int cn = c + 1, rn = cn >> 5, jn = cn & 31;
            const int coln = (rn & 1) ? (LL - 1 - jn) : jn;
            float4 v;
            if (jn == 0) {
                v.x = s.hv[0][coln][tid]; v.y = s.hv[1][coln][tid];
                v.z = s.hv[2][coln][tid]; v.w = s.hv[3][coln][tid];
            } else {
                v.x = h0 + s.hv[0][coln][tid]; v.y = h1 + s.hv[1][coln][tid];
                v.z = h2 + s.hv[2][coln][tid]; v.w = h3 + s.hv[3][coln][tid];
            }
            *(float4*)&s.inp[buf ^ 1][2 + tid][0] = v;
            if (tid == 0) {
                float4 e0, e1;
                float* x0 = &e0.x; float* x1 = &e1.x;
                #pragma unroll
                for (int si = 0; si < SPB; ++si) {
                    const float xh = (jn == 0) ? 0.f
                                   : (float)((s.sbits[si][rn] >> col) & 1u);
                    const float xv = (rn == 0) ? 0.f
                                   : (float)((s.sbits[si][rn - 1] >> coln) & 1u);
                    x0[si] = xh + xv;
                    x1[si] = 2.f - xh - xv;
                }
                *(float4*)&s.inp[buf ^ 1][0][0] = e0;
                *(float4*)&s.inp[buf ^ 1][1][0] = e1;
            }
        }
        __syncthreads();

        // cheap: just stash the pre-activation dot; exp/log deferred to bulk pass
        if (tid < SPB) {
            s.pre[cell][tid] = s.red[buf][0][tid] + s.red[buf][1][tid]
                             + s.red[buf][2][tid] + s.red[buf][3][tid];
        }
    }

    // ---------------- bulk log-prob pass ----------------
    __syncthreads();
    float lp0 = 0.f, lp1 = 0.f, lp2 = 0.f, lp3 = 0.f;
    for (int c = tid; c < NCELL; c += NTHR) {
        const float bfv = __ldg(gBf + c);
        const float4 pr = *(const float4*)&s.pre[c][0];
        const int row = c >> 5, bit = c & 31;
        {
            const float z = pr.x + bfv;
            const float xh = 1.f / (1.f + __expf(-z));
            const float m = (float)((s.sbits[0][row] >> bit) & 1u);
            lp0 += m * __logf(xh + EPSF) + (1.f - m) * __logf(1.f - xh + EPSF);
        }
        {
            const float z = pr.y + bfv;
            const float xh = 1.f / (1.f + __expf(-z));
            const float m = (float)((s.sbits[1][row] >> bit) & 1u);
            lp1 += m * __logf(xh + EPSF) + (1.f - m) * __logf(1.f - xh + EPSF);
        }
        {
            const float z = pr.z + bfv;
            const float xh = 1.f / (1.f + __expf(-z));
            const float m = (float)((s.sbits[2][row] >> bit) & 1u);
            lp2 += m * __logf(xh + EPSF) + (1.f - m) * __logf(1.f - xh + EPSF);
        }
        {
            const float z = pr.w + bfv;
            const float xh = 1.f / (1.f + __expf(-z));
            const float m = (float)((s.sbits[3][row] >> bit) & 1u);
            lp3 += m * __logf(xh + EPSF) + (1.f - m) * __logf(1.f - xh + EPSF);
        }
    }
    // reduce 128 partials per sample (reuse W[0] area as scratch)
    float* rb = &s.W[0][0];
    rb[tid * 4 + 0] = lp0; rb[tid * 4 + 1] = lp1;
    rb[tid * 4 + 2] = lp2; rb[tid * 4 + 3] = lp3;
    __syncthreads();
    if (tid < SPB) {
        float acc = 0.f;
        #pragma unroll 8
        for (int t = 0; t < NTHR; ++t) acc += rb[t * 4 + tid];
        out[blk * SPB + tid] = acc;
    }
}

extern "C" void kernel_launch(void* const* d_in, const int* in_sizes, int n_in,
                              void* d_out, int out_size) {
    const float* samples = (const float*)d_in[0];
    const float* W1      = (const float*)d_in[1];
    const float* b1      = (const float*)d_in[2];
    const float* Wf      = (const float*)d_in[3];
    const float* bf      = (const float*)d_in[4];
    float* out = (float*)d_out;

    prep_kernel<<<NCELL, 256>>>(W1);

    const size_t smem = sizeof(Smem);
    cudaFuncSetAttribute(rnn2d_kernel, cudaFuncAttributeMaxDynamicSharedMemorySize, (int)smem);
    rnn2d_kernel<<<NBLK, NTHR, smem>>>(samples, b1, Wf, bf, out);
}